// round 1
// baseline (speedup 1.0000x reference)
#include <cuda_runtime.h>
#include <math.h>

#define BB 2
#define LL 2048
#define DD 2048
#define HV 32
#define HK 16
#define DK 128
#define DV 128
#define KCONV 4
#define KEY_DIM 2048
#define VAL_DIM 4096
#define CONV_DIM 8192
#define BL (BB*LL)

__device__ float g_mixed[(size_t)BL * CONV_DIM];
__device__ float g_conv [(size_t)BL * CONV_DIM];
__device__ float g_z    [(size_t)BL * VAL_DIM];
__device__ float g_core [(size_t)BL * VAL_DIM];
__device__ float g_gated[(size_t)BL * VAL_DIM];
__device__ float g_gvals[(size_t)BL * HV];
__device__ float g_beta [(size_t)BL * HV];

// ---------------------------------------------------------------------------
// SGEMM: C[M,N] = A[M,K] @ B[K,N], row-major; M,N % 128 == 0, K % 8 == 0
// ---------------------------------------------------------------------------
__global__ __launch_bounds__(256) void sgemm128(
    const float* __restrict__ A, const float* __restrict__ B,
    float* __restrict__ C, int M, int N, int K)
{
    __shared__ float As[8][128];
    __shared__ float Bs[8][128];

    const int tid  = threadIdx.x;
    const int brow = blockIdx.y;
    const int bcol = blockIdx.x;

    const int aRow = tid >> 1;
    const int aCol = (tid & 1) * 4;
    const int bRow = tid >> 5;
    const int bCol = (tid & 31) * 4;

    const int ty = (tid >> 4) * 8;
    const int tx = (tid & 15) * 8;

    const float* Ablk = A + (size_t)brow * 128 * K;
    const float* Bblk = B + (size_t)bcol * 128;

    float acc[8][8];
    #pragma unroll
    for (int i = 0; i < 8; i++)
        #pragma unroll
        for (int j = 0; j < 8; j++) acc[i][j] = 0.f;

    for (int k0 = 0; k0 < K; k0 += 8) {
        float4 a4 = *(const float4*)&Ablk[(size_t)aRow * K + k0 + aCol];
        As[aCol + 0][aRow] = a4.x;
        As[aCol + 1][aRow] = a4.y;
        As[aCol + 2][aRow] = a4.z;
        As[aCol + 3][aRow] = a4.w;
        float4 b4 = *(const float4*)&Bblk[(size_t)(k0 + bRow) * N + bCol];
        *(float4*)&Bs[bRow][bCol] = b4;
        __syncthreads();

        #pragma unroll
        for (int kk = 0; kk < 8; kk++) {
            float ar[8], br[8];
            #pragma unroll
            for (int i = 0; i < 8; i++) ar[i] = As[kk][ty + i];
            #pragma unroll
            for (int j = 0; j < 8; j++) br[j] = Bs[kk][tx + j];
            #pragma unroll
            for (int i = 0; i < 8; i++)
                #pragma unroll
                for (int j = 0; j < 8; j++)
                    acc[i][j] = fmaf(ar[i], br[j], acc[i][j]);
        }
        __syncthreads();
    }

    #pragma unroll
    for (int i = 0; i < 8; i++) {
        size_t row  = (size_t)(brow * 128 + ty + i);
        size_t base = row * N + bcol * 128 + tx;
        float4 v0 = make_float4(acc[i][0], acc[i][1], acc[i][2], acc[i][3]);
        float4 v1 = make_float4(acc[i][4], acc[i][5], acc[i][6], acc[i][7]);
        *(float4*)&C[base]     = v0;
        *(float4*)&C[base + 4] = v1;
    }
}

// ---------------------------------------------------------------------------
// beta / g projections + activations
// ---------------------------------------------------------------------------
__global__ __launch_bounds__(128) void bg_kernel(
    const float* __restrict__ hs, const float* __restrict__ W_b,
    const float* __restrict__ W_a, const float* __restrict__ dt_bias,
    const float* __restrict__ A_log)
{
    __shared__ float row[DD];
    const int bl  = blockIdx.x;
    const int tid = threadIdx.x;

    for (int i = tid; i < DD; i += 128)
        row[i] = hs[(size_t)bl * DD + i];
    __syncthreads();

    if (tid < 64) {
        const int h = tid & 31;
        const bool isA = tid >= 32;
        const float* W = isA ? W_a : W_b;
        float acc = 0.f;
        #pragma unroll 8
        for (int i = 0; i < DD; i++)
            acc = fmaf(row[i], W[i * HV + h], acc);
        if (isA) {
            float x  = acc + dt_bias[h];
            float sp = (x > 20.f) ? x : log1pf(expf(x));
            g_gvals[(size_t)bl * HV + h] = -expf(A_log[h]) * sp;
        } else {
            g_beta[(size_t)bl * HV + h] = 1.f / (1.f + expf(-acc));
        }
    }
}

// ---------------------------------------------------------------------------
// causal depthwise conv(K=4) + SiLU + l2norm(q,k) + q*DK^-0.5
// ---------------------------------------------------------------------------
__global__ __launch_bounds__(128) void conv_kernel(const float* __restrict__ conv_w)
{
    const int grp = blockIdx.x;          // 0..63 channel groups of 128
    const int bl  = blockIdx.y;
    const int l   = bl & (LL - 1);
    const int tid = threadIdx.x;
    const int c   = grp * 128 + tid;

    const float w0 = conv_w[c * 4 + 0];
    const float w1 = conv_w[c * 4 + 1];
    const float w2 = conv_w[c * 4 + 2];
    const float w3 = conv_w[c * 4 + 3];

    const size_t base = (size_t)bl * CONV_DIM + c;
    float acc = g_mixed[base] * w3;
    if (l >= 1) acc = fmaf(g_mixed[base - 1 * CONV_DIM], w2, acc);
    if (l >= 2) acc = fmaf(g_mixed[base - 2 * CONV_DIM], w1, acc);
    if (l >= 3) acc = fmaf(g_mixed[base - 3 * CONV_DIM], w0, acc);

    float s = acc / (1.f + expf(-acc));

    if (grp < 32) {
        __shared__ float red[4];
        float ss = s * s;
        #pragma unroll
        for (int o = 16; o; o >>= 1)
            ss += __shfl_xor_sync(0xffffffffu, ss, o);
        if ((tid & 31) == 0) red[tid >> 5] = ss;
        __syncthreads();
        float tot = red[0] + red[1] + red[2] + red[3];
        s *= rsqrtf(tot + 1e-6f);
        if (grp < 16) s *= 0.08838834764831845f;   // DK^-0.5
    }
    g_conv[base] = s;
}

// ---------------------------------------------------------------------------
// Gated delta-rule scan: block per (h,b); thread owns column dv; S in regs
// ---------------------------------------------------------------------------
__global__ __launch_bounds__(128) void scan_kernel()
{
    const int h   = blockIdx.x;
    const int b   = blockIdx.y;
    const int tid = threadIdx.x;
    const int hk  = h >> 1;              // repeat_interleave source head

    __shared__ float ksm[128];
    __shared__ float qsm[128];

    float S[128];
    #pragma unroll
    for (int i = 0; i < 128; i++) S[i] = 0.f;

    const size_t rowbase = (size_t)b * LL * CONV_DIM;
    const int qc = hk * 128 + tid;
    const int kc = KEY_DIM + hk * 128 + tid;
    const int vc = 2 * KEY_DIM + h * 128 + tid;

    for (int t = 0; t < LL; t++) {
        const size_t off = rowbase + (size_t)t * CONV_DIM;
        ksm[tid] = g_conv[off + kc];
        qsm[tid] = g_conv[off + qc];
        const float vt = g_conv[off + vc];
        const int sidx = (b * LL + t) * HV + h;
        const float gt = g_gvals[sidx];
        const float bt = g_beta[sidx];
        __syncthreads();

        const float eg = expf(gt);
        const float4* k4 = (const float4*)ksm;
        const float4* q4 = (const float4*)qsm;

        float kv = 0.f;
        #pragma unroll
        for (int j = 0; j < 32; j++) {
            float4 kk = k4[j];
            S[4*j+0] *= eg; kv = fmaf(kk.x, S[4*j+0], kv);
            S[4*j+1] *= eg; kv = fmaf(kk.y, S[4*j+1], kv);
            S[4*j+2] *= eg; kv = fmaf(kk.z, S[4*j+2], kv);
            S[4*j+3] *= eg; kv = fmaf(kk.w, S[4*j+3], kv);
        }
        const float delta = (vt - kv) * bt;

        float o = 0.f;
        #pragma unroll
        for (int j = 0; j < 32; j++) {
            float4 kk = k4[j];
            float4 qq = q4[j];
            S[4*j+0] = fmaf(kk.x, delta, S[4*j+0]); o = fmaf(qq.x, S[4*j+0], o);
            S[4*j+1] = fmaf(kk.y, delta, S[4*j+1]); o = fmaf(qq.y, S[4*j+1], o);
            S[4*j+2] = fmaf(kk.z, delta, S[4*j+2]); o = fmaf(qq.z, S[4*j+2], o);
            S[4*j+3] = fmaf(kk.w, delta, S[4*j+3]); o = fmaf(qq.w, S[4*j+3], o);
        }
        g_core[((size_t)(b * LL + t)) * VAL_DIM + h * 128 + tid] = o;
        __syncthreads();
    }
}

// ---------------------------------------------------------------------------
// Gated RMSNorm: x = core*silu(z); x * rsqrt(mean(x^2)+1e-6) * norm_w
// ---------------------------------------------------------------------------
__global__ __launch_bounds__(128) void gatednorm_kernel(const float* __restrict__ norm_w)
{
    const int h   = blockIdx.x;
    const int bl  = blockIdx.y;
    const int tid = threadIdx.x;
    const size_t idx = (size_t)bl * VAL_DIM + h * 128 + tid;

    float c  = g_core[idx];
    float zz = g_z[idx];
    float gz = zz / (1.f + expf(-zz));
    float x  = c * gz;

    __shared__ float red[4];
    float ss = x * x;
    #pragma unroll
    for (int o = 16; o; o >>= 1)
        ss += __shfl_xor_sync(0xffffffffu, ss, o);
    if ((tid & 31) == 0) red[tid >> 5] = ss;
    __syncthreads();
    float tot  = red[0] + red[1] + red[2] + red[3];
    float mean = tot * (1.f / 128.f);

    g_gated[idx] = x * rsqrtf(mean + 1e-6f) * norm_w[tid];
}

// ---------------------------------------------------------------------------
extern "C" void kernel_launch(void* const* d_in, const int* in_sizes, int n_in,
                              void* d_out, int out_size)
{
    const float* hs      = (const float*)d_in[0];
    const float* W_qkv   = (const float*)d_in[1];
    const float* W_z     = (const float*)d_in[2];
    const float* W_b     = (const float*)d_in[3];
    const float* W_a     = (const float*)d_in[4];
    const float* conv_w  = (const float*)d_in[5];
    const float* dt_bias = (const float*)d_in[6];
    const float* A_log   = (const float*)d_in[7];
    const float* norm_w  = (const float*)d_in[8];
    const float* W_out   = (const float*)d_in[9];
    float* out = (float*)d_out;

    float* mixed_ptr; cudaGetSymbolAddress((void**)&mixed_ptr, g_mixed);
    float* z_ptr;     cudaGetSymbolAddress((void**)&z_ptr,     g_z);
    float* gated_ptr; cudaGetSymbolAddress((void**)&gated_ptr, g_gated);

    sgemm128<<<dim3(CONV_DIM/128, BL/128), 256>>>(hs, W_qkv, mixed_ptr, BL, CONV_DIM, DD);
    sgemm128<<<dim3(VAL_DIM/128, BL/128), 256>>>(hs, W_z, z_ptr, BL, VAL_DIM, DD);
    bg_kernel<<<BL, 128>>>(hs, W_b, W_a, dt_bias, A_log);
    conv_kernel<<<dim3(CONV_DIM/128, BL), 128>>>(conv_w);
    scan_kernel<<<dim3(HV, BB), 128>>>();
    gatednorm_kernel<<<dim3(HV, BL), 128>>>(norm_w);
    sgemm128<<<dim3(DD/128, BL/128), 256>>>(gated_ptr, W_out, out, BL, DD, VAL_DIM);
}

// round 2
// speedup vs baseline: 1.8163x; 1.8163x over previous
#include <cuda_runtime.h>
#include <math.h>
#include <stdint.h>

#define BB 2
#define LL 2048
#define DD 2048
#define HV 32
#define HK 16
#define DK 128
#define DV 128
#define KCONV 4
#define KEY_DIM 2048
#define VAL_DIM 4096
#define CONV_DIM 8192
#define BL (BB*LL)

__device__ float g_mixed[(size_t)BL * CONV_DIM];
__device__ float g_conv [(size_t)BL * CONV_DIM];
__device__ float g_z    [(size_t)BL * VAL_DIM];
__device__ float g_core [(size_t)BL * VAL_DIM];
__device__ float g_gated[(size_t)BL * VAL_DIM];
__device__ float g_gvals[(size_t)BL * HV];
__device__ float g_beta [(size_t)BL * HV];

// ---------------------------------------------------------------------------
// TF32 tensor-core GEMM: C[M,N] = A[M,K] @ B[K,N], row-major.
// M,N % 128 == 0, K % 16 == 0.
// 128x128 CTA tile, BK=16 double-buffered, 8 warps of 64x32, m16n8k8 tf32.
// ---------------------------------------------------------------------------
__device__ __forceinline__ uint32_t f2tf(float x) {
    uint32_t r;
    asm("cvt.rna.tf32.f32 %0, %1;" : "=r"(r) : "f"(x));
    return r;
}

#define AS_STRIDE 20   // 16 + 4 pad: rows map to banks {0,20,8,28,16,4,24,12}
#define BS_STRIDE 136  // 128 + 8 pad: (8k + n) % 32 is a bijection per warp read

__global__ __launch_bounds__(256) void gemm_tf32(
    const float* __restrict__ A, const float* __restrict__ B,
    float* __restrict__ C, int M, int N, int K)
{
    __shared__ float As[2][128 * AS_STRIDE];
    __shared__ float Bs[2][16  * BS_STRIDE];

    const int tid  = threadIdx.x;
    const int warp = tid >> 5;
    const int lane = tid & 31;
    const int g    = lane >> 2;   // group id 0..7
    const int t    = lane & 3;    // thread-in-group 0..3

    const int wm = (warp >> 2) * 64;   // warp row offset (0 / 64)
    const int wn = (warp & 3)  * 32;   // warp col offset (0/32/64/96)

    const int brow = blockIdx.y;
    const int bcol = blockIdx.x;

    // global-load assignments
    const int aRow0 = tid >> 1;               // rows via idx = tid, tid+256
    const int aC0   = (tid & 1) * 4;          // wait: 2048 floats, 512 float4
    // idx scheme: idx in [0,512): row = idx>>2, c4 = idx&3
    const int aIdx0 = tid;                    // and tid+256
    const int bIdx0 = tid;                    // and tid+256
    (void)aRow0; (void)aC0;

    float acc[4][4][4];
    #pragma unroll
    for (int mi = 0; mi < 4; mi++)
        #pragma unroll
        for (int ni = 0; ni < 4; ni++)
            #pragma unroll
            for (int r = 0; r < 4; r++) acc[mi][ni][r] = 0.f;

    const float* Ab = A + (size_t)brow * 128 * K;
    const float* Bb = B + (size_t)bcol * 128;

    const int nt = K >> 4;

    // prologue: load tile 0
    {
        #pragma unroll
        for (int it = 0; it < 2; it++) {
            int idx = aIdx0 + it * 256;
            int row = idx >> 2, c4 = (idx & 3) * 4;
            float4 v = *(const float4*)&Ab[(size_t)row * K + c4];
            float* d = &As[0][row * AS_STRIDE + c4];
            d[0] = __uint_as_float(f2tf(v.x));
            d[1] = __uint_as_float(f2tf(v.y));
            d[2] = __uint_as_float(f2tf(v.z));
            d[3] = __uint_as_float(f2tf(v.w));
        }
        #pragma unroll
        for (int it = 0; it < 2; it++) {
            int idx = bIdx0 + it * 256;
            int kr = idx >> 5, c4 = (idx & 31) * 4;
            float4 v = *(const float4*)&Bb[(size_t)kr * N + c4];
            float* d = &Bs[0][kr * BS_STRIDE + c4];
            d[0] = __uint_as_float(f2tf(v.x));
            d[1] = __uint_as_float(f2tf(v.y));
            d[2] = __uint_as_float(f2tf(v.z));
            d[3] = __uint_as_float(f2tf(v.w));
        }
    }
    __syncthreads();

    for (int kt = 0; kt < nt; kt++) {
        const int cur = kt & 1;
        float4 av[2], bv[2];
        const bool more = (kt + 1) < nt;
        if (more) {
            const int k0 = (kt + 1) << 4;
            #pragma unroll
            for (int it = 0; it < 2; it++) {
                int idx = aIdx0 + it * 256;
                int row = idx >> 2, c4 = (idx & 3) * 4;
                av[it] = *(const float4*)&Ab[(size_t)row * K + k0 + c4];
            }
            #pragma unroll
            for (int it = 0; it < 2; it++) {
                int idx = bIdx0 + it * 256;
                int kr = idx >> 5, c4 = (idx & 31) * 4;
                bv[it] = *(const float4*)&Bb[(size_t)(k0 + kr) * N + c4];
            }
        }

        // compute on current buffer
        const float* as = As[cur];
        const float* bs = Bs[cur];
        #pragma unroll
        for (int ks = 0; ks < 2; ks++) {
            const int k0 = ks * 8;
            uint32_t af[4][4], bf[4][2];
            #pragma unroll
            for (int mi = 0; mi < 4; mi++) {
                const int rb = wm + mi * 16;
                af[mi][0] = __float_as_uint(as[(rb + g    ) * AS_STRIDE + k0 + t    ]);
                af[mi][1] = __float_as_uint(as[(rb + g + 8) * AS_STRIDE + k0 + t    ]);
                af[mi][2] = __float_as_uint(as[(rb + g    ) * AS_STRIDE + k0 + t + 4]);
                af[mi][3] = __float_as_uint(as[(rb + g + 8) * AS_STRIDE + k0 + t + 4]);
            }
            #pragma unroll
            for (int ni = 0; ni < 4; ni++) {
                const int nb = wn + ni * 8;
                bf[ni][0] = __float_as_uint(bs[(k0 + t    ) * BS_STRIDE + nb + g]);
                bf[ni][1] = __float_as_uint(bs[(k0 + t + 4) * BS_STRIDE + nb + g]);
            }
            #pragma unroll
            for (int mi = 0; mi < 4; mi++)
                #pragma unroll
                for (int ni = 0; ni < 4; ni++) {
                    asm volatile(
                        "mma.sync.aligned.m16n8k8.row.col.f32.tf32.tf32.f32 "
                        "{%0,%1,%2,%3}, {%4,%5,%6,%7}, {%8,%9}, {%0,%1,%2,%3};"
                        : "+f"(acc[mi][ni][0]), "+f"(acc[mi][ni][1]),
                          "+f"(acc[mi][ni][2]), "+f"(acc[mi][ni][3])
                        : "r"(af[mi][0]), "r"(af[mi][1]), "r"(af[mi][2]), "r"(af[mi][3]),
                          "r"(bf[ni][0]), "r"(bf[ni][1]));
                }
        }

        if (more) {
            const int nxt = cur ^ 1;
            #pragma unroll
            for (int it = 0; it < 2; it++) {
                int idx = aIdx0 + it * 256;
                int row = idx >> 2, c4 = (idx & 3) * 4;
                float* d = &As[nxt][row * AS_STRIDE + c4];
                d[0] = __uint_as_float(f2tf(av[it].x));
                d[1] = __uint_as_float(f2tf(av[it].y));
                d[2] = __uint_as_float(f2tf(av[it].z));
                d[3] = __uint_as_float(f2tf(av[it].w));
            }
            #pragma unroll
            for (int it = 0; it < 2; it++) {
                int idx = bIdx0 + it * 256;
                int kr = idx >> 5, c4 = (idx & 31) * 4;
                float* d = &Bs[nxt][kr * BS_STRIDE + c4];
                d[0] = __uint_as_float(f2tf(bv[it].x));
                d[1] = __uint_as_float(f2tf(bv[it].y));
                d[2] = __uint_as_float(f2tf(bv[it].z));
                d[3] = __uint_as_float(f2tf(bv[it].w));
            }
        }
        __syncthreads();
    }

    // epilogue: c0,c1 at (g, 2t),(g, 2t+1); c2,c3 at (g+8, ...)
    #pragma unroll
    for (int mi = 0; mi < 4; mi++) {
        #pragma unroll
        for (int ni = 0; ni < 4; ni++) {
            const size_t r0 = (size_t)(brow * 128 + wm + mi * 16 + g);
            const size_t cc = (size_t)(bcol * 128 + wn + ni * 8 + 2 * t);
            float2 v0 = make_float2(acc[mi][ni][0], acc[mi][ni][1]);
            float2 v1 = make_float2(acc[mi][ni][2], acc[mi][ni][3]);
            *(float2*)&C[r0 * N + cc]       = v0;
            *(float2*)&C[(r0 + 8) * N + cc] = v1;
        }
    }
}

// ---------------------------------------------------------------------------
// beta / g projections + activations
// ---------------------------------------------------------------------------
__global__ __launch_bounds__(128) void bg_kernel(
    const float* __restrict__ hs, const float* __restrict__ W_b,
    const float* __restrict__ W_a, const float* __restrict__ dt_bias,
    const float* __restrict__ A_log)
{
    __shared__ float row[DD];
    const int bl  = blockIdx.x;
    const int tid = threadIdx.x;

    for (int i = tid; i < DD; i += 128)
        row[i] = hs[(size_t)bl * DD + i];
    __syncthreads();

    if (tid < 64) {
        const int h = tid & 31;
        const bool isA = tid >= 32;
        const float* W = isA ? W_a : W_b;
        float acc = 0.f;
        #pragma unroll 8
        for (int i = 0; i < DD; i++)
            acc = fmaf(row[i], W[i * HV + h], acc);
        if (isA) {
            float x  = acc + dt_bias[h];
            float sp = (x > 20.f) ? x : log1pf(expf(x));
            g_gvals[(size_t)bl * HV + h] = -expf(A_log[h]) * sp;
        } else {
            g_beta[(size_t)bl * HV + h] = 1.f / (1.f + expf(-acc));
        }
    }
}

// ---------------------------------------------------------------------------
// causal depthwise conv(K=4) + SiLU + l2norm(q,k) + q*DK^-0.5
// ---------------------------------------------------------------------------
__global__ __launch_bounds__(128) void conv_kernel(const float* __restrict__ conv_w)
{
    const int grp = blockIdx.x;
    const int bl  = blockIdx.y;
    const int l   = bl & (LL - 1);
    const int tid = threadIdx.x;
    const int c   = grp * 128 + tid;

    const float w0 = conv_w[c * 4 + 0];
    const float w1 = conv_w[c * 4 + 1];
    const float w2 = conv_w[c * 4 + 2];
    const float w3 = conv_w[c * 4 + 3];

    const size_t base = (size_t)bl * CONV_DIM + c;
    float acc = g_mixed[base] * w3;
    if (l >= 1) acc = fmaf(g_mixed[base - 1 * CONV_DIM], w2, acc);
    if (l >= 2) acc = fmaf(g_mixed[base - 2 * CONV_DIM], w1, acc);
    if (l >= 3) acc = fmaf(g_mixed[base - 3 * CONV_DIM], w0, acc);

    float s = acc / (1.f + expf(-acc));

    if (grp < 32) {
        __shared__ float red[4];
        float ss = s * s;
        #pragma unroll
        for (int o = 16; o; o >>= 1)
            ss += __shfl_xor_sync(0xffffffffu, ss, o);
        if ((tid & 31) == 0) red[tid >> 5] = ss;
        __syncthreads();
        float tot = red[0] + red[1] + red[2] + red[3];
        s *= rsqrtf(tot + 1e-6f);
        if (grp < 16) s *= 0.08838834764831845f;
    }
    g_conv[base] = s;
}

// ---------------------------------------------------------------------------
// Gated delta-rule scan: block per (h,b); thread owns column dv; S in regs
// ---------------------------------------------------------------------------
__global__ __launch_bounds__(128) void scan_kernel()
{
    const int h   = blockIdx.x;
    const int b   = blockIdx.y;
    const int tid = threadIdx.x;
    const int hk  = h >> 1;

    __shared__ float ksm[128];
    __shared__ float qsm[128];

    float S[128];
    #pragma unroll
    for (int i = 0; i < 128; i++) S[i] = 0.f;

    const size_t rowbase = (size_t)b * LL * CONV_DIM;
    const int qc = hk * 128 + tid;
    const int kc = KEY_DIM + hk * 128 + tid;
    const int vc = 2 * KEY_DIM + h * 128 + tid;

    for (int t = 0; t < LL; t++) {
        const size_t off = rowbase + (size_t)t * CONV_DIM;
        ksm[tid] = g_conv[off + kc];
        qsm[tid] = g_conv[off + qc];
        const float vt = g_conv[off + vc];
        const int sidx = (b * LL + t) * HV + h;
        const float gt = g_gvals[sidx];
        const float bt = g_beta[sidx];
        __syncthreads();

        const float eg = expf(gt);
        const float4* k4 = (const float4*)ksm;
        const float4* q4 = (const float4*)qsm;

        float kv = 0.f;
        #pragma unroll
        for (int j = 0; j < 32; j++) {
            float4 kk = k4[j];
            S[4*j+0] *= eg; kv = fmaf(kk.x, S[4*j+0], kv);
            S[4*j+1] *= eg; kv = fmaf(kk.y, S[4*j+1], kv);
            S[4*j+2] *= eg; kv = fmaf(kk.z, S[4*j+2], kv);
            S[4*j+3] *= eg; kv = fmaf(kk.w, S[4*j+3], kv);
        }
        const float delta = (vt - kv) * bt;

        float o = 0.f;
        #pragma unroll
        for (int j = 0; j < 32; j++) {
            float4 kk = k4[j];
            float4 qq = q4[j];
            S[4*j+0] = fmaf(kk.x, delta, S[4*j+0]); o = fmaf(qq.x, S[4*j+0], o);
            S[4*j+1] = fmaf(kk.y, delta, S[4*j+1]); o = fmaf(qq.y, S[4*j+1], o);
            S[4*j+2] = fmaf(kk.z, delta, S[4*j+2]); o = fmaf(qq.z, S[4*j+2], o);
            S[4*j+3] = fmaf(kk.w, delta, S[4*j+3]); o = fmaf(qq.w, S[4*j+3], o);
        }
        g_core[((size_t)(b * LL + t)) * VAL_DIM + h * 128 + tid] = o;
        __syncthreads();
    }
}

// ---------------------------------------------------------------------------
// Gated RMSNorm
// ---------------------------------------------------------------------------
__global__ __launch_bounds__(128) void gatednorm_kernel(const float* __restrict__ norm_w)
{
    const int h   = blockIdx.x;
    const int bl  = blockIdx.y;
    const int tid = threadIdx.x;
    const size_t idx = (size_t)bl * VAL_DIM + h * 128 + tid;

    float c  = g_core[idx];
    float zz = g_z[idx];
    float gz = zz / (1.f + expf(-zz));
    float x  = c * gz;

    __shared__ float red[4];
    float ss = x * x;
    #pragma unroll
    for (int o = 16; o; o >>= 1)
        ss += __shfl_xor_sync(0xffffffffu, ss, o);
    if ((tid & 31) == 0) red[tid >> 5] = ss;
    __syncthreads();
    float tot  = red[0] + red[1] + red[2] + red[3];
    float mean = tot * (1.f / 128.f);

    g_gated[idx] = x * rsqrtf(mean + 1e-6f) * norm_w[tid];
}

// ---------------------------------------------------------------------------
extern "C" void kernel_launch(void* const* d_in, const int* in_sizes, int n_in,
                              void* d_out, int out_size)
{
    const float* hs      = (const float*)d_in[0];
    const float* W_qkv   = (const float*)d_in[1];
    const float* W_z     = (const float*)d_in[2];
    const float* W_b     = (const float*)d_in[3];
    const float* W_a     = (const float*)d_in[4];
    const float* conv_w  = (const float*)d_in[5];
    const float* dt_bias = (const float*)d_in[6];
    const float* A_log   = (const float*)d_in[7];
    const float* norm_w  = (const float*)d_in[8];
    const float* W_out   = (const float*)d_in[9];
    float* out = (float*)d_out;

    float* mixed_ptr; cudaGetSymbolAddress((void**)&mixed_ptr, g_mixed);
    float* z_ptr;     cudaGetSymbolAddress((void**)&z_ptr,     g_z);
    float* gated_ptr; cudaGetSymbolAddress((void**)&gated_ptr, g_gated);

    gemm_tf32<<<dim3(CONV_DIM/128, BL/128), 256>>>(hs, W_qkv, mixed_ptr, BL, CONV_DIM, DD);
    gemm_tf32<<<dim3(VAL_DIM/128, BL/128), 256>>>(hs, W_z, z_ptr, BL, VAL_DIM, DD);
    bg_kernel<<<BL, 128>>>(hs, W_b, W_a, dt_bias, A_log);
    conv_kernel<<<dim3(CONV_DIM/128, BL), 128>>>(conv_w);
    scan_kernel<<<dim3(HV, BB), 128>>>();
    gatednorm_kernel<<<dim3(HV, BL), 128>>>(norm_w);
    gemm_tf32<<<dim3(DD/128, BL/128), 256>>>(gated_ptr, W_out, out, BL, DD, VAL_DIM);
}

// round 3
// speedup vs baseline: 1.8662x; 1.0274x over previous
#include <cuda_runtime.h>
#include <math.h>
#include <stdint.h>

#define BB 2
#define LL 2048
#define DD 2048
#define HV 32
#define HK 16
#define DK 128
#define DV 128
#define KCONV 4
#define KEY_DIM 2048
#define VAL_DIM 4096
#define CONV_DIM 8192
#define BL (BB*LL)

__device__ float g_mixed[(size_t)BL * CONV_DIM];
__device__ float g_conv [(size_t)BL * CONV_DIM];
__device__ float g_z    [(size_t)BL * VAL_DIM];
__device__ float g_core [(size_t)BL * VAL_DIM];
__device__ float g_gated[(size_t)BL * VAL_DIM];
__device__ float g_gvals[(size_t)BL * HV];
__device__ float g_beta [(size_t)BL * HV];

// ---------------------------------------------------------------------------
// TF32 tensor-core GEMM with 4-stage cp.async pipeline.
// C[M,N] = A[M,K] @ B[K,N], row-major; M,N % 128 == 0, K % 16 == 0.
// 128x128 CTA tile, BK=16 per stage, 8 warps of 64x32, m16n8k8 tf32.
// ---------------------------------------------------------------------------
__device__ __forceinline__ float f2tf(float x) {
    uint32_t r;
    asm("cvt.rna.tf32.f32 %0, %1;" : "=r"(r) : "f"(x));
    return __uint_as_float(r);
}

#define STAGES 4
#define GBK 16
#define AS_STRIDE 20    // 16 + 4 pad: row starts hit distinct 4-word groups
#define BS_STRIDE 136   // 128 + 8 pad: (8k + n) bijection onto banks
#define AS_SZ (128 * AS_STRIDE)
#define BS_SZ (GBK * BS_STRIDE)
#define STAGE_SZ (AS_SZ + BS_SZ)
#define GEMM_SMEM_BYTES (STAGES * STAGE_SZ * 4)

__device__ __forceinline__ void cp16(uint32_t dst, const float* src) {
    asm volatile("cp.async.cg.shared.global [%0], [%1], 16;\n" :: "r"(dst), "l"(src));
}

__global__ __launch_bounds__(256, 2) void gemm_tf32(
    const float* __restrict__ A, const float* __restrict__ B,
    float* __restrict__ C, int M, int N, int K)
{
    extern __shared__ float sm[];
    uint32_t smb;
    asm("{ .reg .u64 t; cvta.to.shared.u64 t, %1; cvt.u32.u64 %0, t; }"
        : "=r"(smb) : "l"(sm));

    const int tid  = threadIdx.x;
    const int warp = tid >> 5;
    const int lane = tid & 31;
    const int g    = lane >> 2;
    const int t    = lane & 3;

    const int wm = (warp >> 2) * 64;
    const int wn = (warp & 3)  * 32;

    const int brow = blockIdx.y;
    const int bcol = blockIdx.x;

    const float* Ab = A + (size_t)brow * 128 * K;
    const float* Bb = B + (size_t)bcol * 128;

    // cp.async chunk assignments (512 x 16B for A, 512 x 16B for B per stage)
    const int aRow0 = tid >> 2;           // + 64 for second chunk
    const int aC    = (tid & 3) * 4;
    const int bKr0  = tid >> 5;           // + 8 for second chunk
    const int bC    = (tid & 31) * 4;

    float acc[4][4][4];
    #pragma unroll
    for (int mi = 0; mi < 4; mi++)
        #pragma unroll
        for (int ni = 0; ni < 4; ni++)
            #pragma unroll
            for (int r = 0; r < 4; r++) acc[mi][ni][r] = 0.f;

    const int nt = K >> 4;

    // ---- prologue: issue STAGES-1 stages ----
    #pragma unroll
    for (int s = 0; s < STAGES - 1; s++) {
        const int k0 = s * GBK;
        uint32_t sb = smb + (uint32_t)(s * STAGE_SZ) * 4u;
        cp16(sb + (uint32_t)(aRow0 * AS_STRIDE + aC) * 4u,
             Ab + (size_t)aRow0 * K + k0 + aC);
        cp16(sb + (uint32_t)((aRow0 + 64) * AS_STRIDE + aC) * 4u,
             Ab + (size_t)(aRow0 + 64) * K + k0 + aC);
        uint32_t bb = sb + (uint32_t)AS_SZ * 4u;
        cp16(bb + (uint32_t)(bKr0 * BS_STRIDE + bC) * 4u,
             Bb + (size_t)(k0 + bKr0) * N + bC);
        cp16(bb + (uint32_t)((bKr0 + 8) * BS_STRIDE + bC) * 4u,
             Bb + (size_t)(k0 + bKr0 + 8) * N + bC);
        asm volatile("cp.async.commit_group;\n");
    }

    for (int kt = 0; kt < nt; kt++) {
        asm volatile("cp.async.wait_group %0;\n" :: "n"(STAGES - 2));
        __syncthreads();

        // ---- prefetch stage kt+STAGES-1 ----
        const int pf = kt + STAGES - 1;
        if (pf < nt) {
            const int k0 = pf * GBK;
            uint32_t sb = smb + (uint32_t)((pf % STAGES) * STAGE_SZ) * 4u;
            cp16(sb + (uint32_t)(aRow0 * AS_STRIDE + aC) * 4u,
                 Ab + (size_t)aRow0 * K + k0 + aC);
            cp16(sb + (uint32_t)((aRow0 + 64) * AS_STRIDE + aC) * 4u,
                 Ab + (size_t)(aRow0 + 64) * K + k0 + aC);
            uint32_t bb = sb + (uint32_t)AS_SZ * 4u;
            cp16(bb + (uint32_t)(bKr0 * BS_STRIDE + bC) * 4u,
                 Bb + (size_t)(k0 + bKr0) * N + bC);
            cp16(bb + (uint32_t)((bKr0 + 8) * BS_STRIDE + bC) * 4u,
                 Bb + (size_t)(k0 + bKr0 + 8) * N + bC);
        }
        asm volatile("cp.async.commit_group;\n");

        // ---- compute on stage kt%STAGES ----
        const float* as = sm + (size_t)(kt % STAGES) * STAGE_SZ;
        const float* bs = as + AS_SZ;

        #pragma unroll
        for (int ks = 0; ks < 2; ks++) {
            const int k0 = ks * 8;
            uint32_t af[4][4], bf[4][2];
            #pragma unroll
            for (int mi = 0; mi < 4; mi++) {
                const int rb = wm + mi * 16;
                af[mi][0] = __float_as_uint(f2tf(as[(rb + g    ) * AS_STRIDE + k0 + t    ]));
                af[mi][1] = __float_as_uint(f2tf(as[(rb + g + 8) * AS_STRIDE + k0 + t    ]));
                af[mi][2] = __float_as_uint(f2tf(as[(rb + g    ) * AS_STRIDE + k0 + t + 4]));
                af[mi][3] = __float_as_uint(f2tf(as[(rb + g + 8) * AS_STRIDE + k0 + t + 4]));
            }
            #pragma unroll
            for (int ni = 0; ni < 4; ni++) {
                const int nb = wn + ni * 8;
                bf[ni][0] = __float_as_uint(f2tf(bs[(k0 + t    ) * BS_STRIDE + nb + g]));
                bf[ni][1] = __float_as_uint(f2tf(bs[(k0 + t + 4) * BS_STRIDE + nb + g]));
            }
            #pragma unroll
            for (int mi = 0; mi < 4; mi++)
                #pragma unroll
                for (int ni = 0; ni < 4; ni++) {
                    asm volatile(
                        "mma.sync.aligned.m16n8k8.row.col.f32.tf32.tf32.f32 "
                        "{%0,%1,%2,%3}, {%4,%5,%6,%7}, {%8,%9}, {%0,%1,%2,%3};"
                        : "+f"(acc[mi][ni][0]), "+f"(acc[mi][ni][1]),
                          "+f"(acc[mi][ni][2]), "+f"(acc[mi][ni][3])
                        : "r"(af[mi][0]), "r"(af[mi][1]), "r"(af[mi][2]), "r"(af[mi][3]),
                          "r"(bf[ni][0]), "r"(bf[ni][1]));
                }
        }
    }

    #pragma unroll
    for (int mi = 0; mi < 4; mi++) {
        #pragma unroll
        for (int ni = 0; ni < 4; ni++) {
            const size_t r0 = (size_t)(brow * 128 + wm + mi * 16 + g);
            const size_t cc = (size_t)(bcol * 128 + wn + ni * 8 + 2 * t);
            float2 v0 = make_float2(acc[mi][ni][0], acc[mi][ni][1]);
            float2 v1 = make_float2(acc[mi][ni][2], acc[mi][ni][3]);
            *(float2*)&C[r0 * N + cc]       = v0;
            *(float2*)&C[(r0 + 8) * N + cc] = v1;
        }
    }
}

// ---------------------------------------------------------------------------
// beta / g projections + activations
// ---------------------------------------------------------------------------
__global__ __launch_bounds__(128) void bg_kernel(
    const float* __restrict__ hs, const float* __restrict__ W_b,
    const float* __restrict__ W_a, const float* __restrict__ dt_bias,
    const float* __restrict__ A_log)
{
    __shared__ float row[DD];
    const int bl  = blockIdx.x;
    const int tid = threadIdx.x;

    for (int i = tid; i < DD; i += 128)
        row[i] = hs[(size_t)bl * DD + i];
    __syncthreads();

    if (tid < 64) {
        const int h = tid & 31;
        const bool isA = tid >= 32;
        const float* W = isA ? W_a : W_b;
        float acc = 0.f;
        #pragma unroll 8
        for (int i = 0; i < DD; i++)
            acc = fmaf(row[i], W[i * HV + h], acc);
        if (isA) {
            float x  = acc + dt_bias[h];
            float sp = (x > 20.f) ? x : log1pf(expf(x));
            g_gvals[(size_t)bl * HV + h] = -expf(A_log[h]) * sp;
        } else {
            g_beta[(size_t)bl * HV + h] = 1.f / (1.f + expf(-acc));
        }
    }
}

// ---------------------------------------------------------------------------
// causal depthwise conv(K=4) + SiLU + l2norm(q,k) + q*DK^-0.5
// ---------------------------------------------------------------------------
__global__ __launch_bounds__(128) void conv_kernel(const float* __restrict__ conv_w)
{
    const int grp = blockIdx.x;
    const int bl  = blockIdx.y;
    const int l   = bl & (LL - 1);
    const int tid = threadIdx.x;
    const int c   = grp * 128 + tid;

    const float w0 = conv_w[c * 4 + 0];
    const float w1 = conv_w[c * 4 + 1];
    const float w2 = conv_w[c * 4 + 2];
    const float w3 = conv_w[c * 4 + 3];

    const size_t base = (size_t)bl * CONV_DIM + c;
    float acc = g_mixed[base] * w3;
    if (l >= 1) acc = fmaf(g_mixed[base - 1 * CONV_DIM], w2, acc);
    if (l >= 2) acc = fmaf(g_mixed[base - 2 * CONV_DIM], w1, acc);
    if (l >= 3) acc = fmaf(g_mixed[base - 3 * CONV_DIM], w0, acc);

    float s = acc / (1.f + expf(-acc));

    if (grp < 32) {
        __shared__ float red[4];
        float ss = s * s;
        #pragma unroll
        for (int o = 16; o; o >>= 1)
            ss += __shfl_xor_sync(0xffffffffu, ss, o);
        if ((tid & 31) == 0) red[tid >> 5] = ss;
        __syncthreads();
        float tot = red[0] + red[1] + red[2] + red[3];
        s *= rsqrtf(tot + 1e-6f);
        if (grp < 16) s *= 0.08838834764831845f;
    }
    g_conv[base] = s;
}

// ---------------------------------------------------------------------------
// Gated delta-rule scan: block per (h,b); thread owns column dv; S in regs
// ---------------------------------------------------------------------------
__global__ __launch_bounds__(128) void scan_kernel()
{
    const int h   = blockIdx.x;
    const int b   = blockIdx.y;
    const int tid = threadIdx.x;
    const int hk  = h >> 1;

    __shared__ float ksm[128];
    __shared__ float qsm[128];

    float S[128];
    #pragma unroll
    for (int i = 0; i < 128; i++) S[i] = 0.f;

    const size_t rowbase = (size_t)b * LL * CONV_DIM;
    const int qc = hk * 128 + tid;
    const int kc = KEY_DIM + hk * 128 + tid;
    const int vc = 2 * KEY_DIM + h * 128 + tid;

    for (int t = 0; t < LL; t++) {
        const size_t off = rowbase + (size_t)t * CONV_DIM;
        ksm[tid] = g_conv[off + kc];
        qsm[tid] = g_conv[off + qc];
        const float vt = g_conv[off + vc];
        const int sidx = (b * LL + t) * HV + h;
        const float gt = g_gvals[sidx];
        const float bt = g_beta[sidx];
        __syncthreads();

        const float eg = expf(gt);
        const float4* k4 = (const float4*)ksm;
        const float4* q4 = (const float4*)qsm;

        float kv = 0.f;
        #pragma unroll
        for (int j = 0; j < 32; j++) {
            float4 kk = k4[j];
            S[4*j+0] *= eg; kv = fmaf(kk.x, S[4*j+0], kv);
            S[4*j+1] *= eg; kv = fmaf(kk.y, S[4*j+1], kv);
            S[4*j+2] *= eg; kv = fmaf(kk.z, S[4*j+2], kv);
            S[4*j+3] *= eg; kv = fmaf(kk.w, S[4*j+3], kv);
        }
        const float delta = (vt - kv) * bt;

        float o = 0.f;
        #pragma unroll
        for (int j = 0; j < 32; j++) {
            float4 kk = k4[j];
            float4 qq = q4[j];
            S[4*j+0] = fmaf(kk.x, delta, S[4*j+0]); o = fmaf(qq.x, S[4*j+0], o);
            S[4*j+1] = fmaf(kk.y, delta, S[4*j+1]); o = fmaf(qq.y, S[4*j+1], o);
            S[4*j+2] = fmaf(kk.z, delta, S[4*j+2]); o = fmaf(qq.z, S[4*j+2], o);
            S[4*j+3] = fmaf(kk.w, delta, S[4*j+3]); o = fmaf(qq.w, S[4*j+3], o);
        }
        g_core[((size_t)(b * LL + t)) * VAL_DIM + h * 128 + tid] = o;
        __syncthreads();
    }
}

// ---------------------------------------------------------------------------
// Gated RMSNorm
// ---------------------------------------------------------------------------
__global__ __launch_bounds__(128) void gatednorm_kernel(const float* __restrict__ norm_w)
{
    const int h   = blockIdx.x;
    const int bl  = blockIdx.y;
    const int tid = threadIdx.x;
    const size_t idx = (size_t)bl * VAL_DIM + h * 128 + tid;

    float c  = g_core[idx];
    float zz = g_z[idx];
    float gz = zz / (1.f + expf(-zz));
    float x  = c * gz;

    __shared__ float red[4];
    float ss = x * x;
    #pragma unroll
    for (int o = 16; o; o >>= 1)
        ss += __shfl_xor_sync(0xffffffffu, ss, o);
    if ((tid & 31) == 0) red[tid >> 5] = ss;
    __syncthreads();
    float tot  = red[0] + red[1] + red[2] + red[3];
    float mean = tot * (1.f / 128.f);

    g_gated[idx] = x * rsqrtf(mean + 1e-6f) * norm_w[tid];
}

// ---------------------------------------------------------------------------
extern "C" void kernel_launch(void* const* d_in, const int* in_sizes, int n_in,
                              void* d_out, int out_size)
{
    const float* hs      = (const float*)d_in[0];
    const float* W_qkv   = (const float*)d_in[1];
    const float* W_z     = (const float*)d_in[2];
    const float* W_b     = (const float*)d_in[3];
    const float* W_a     = (const float*)d_in[4];
    const float* conv_w  = (const float*)d_in[5];
    const float* dt_bias = (const float*)d_in[6];
    const float* A_log   = (const float*)d_in[7];
    const float* norm_w  = (const float*)d_in[8];
    const float* W_out   = (const float*)d_in[9];
    float* out = (float*)d_out;

    float* mixed_ptr; cudaGetSymbolAddress((void**)&mixed_ptr, g_mixed);
    float* z_ptr;     cudaGetSymbolAddress((void**)&z_ptr,     g_z);
    float* gated_ptr; cudaGetSymbolAddress((void**)&gated_ptr, g_gated);

    cudaFuncSetAttribute(gemm_tf32,
        cudaFuncAttributeMaxDynamicSharedMemorySize, GEMM_SMEM_BYTES);

    gemm_tf32<<<dim3(CONV_DIM/128, BL/128), 256, GEMM_SMEM_BYTES>>>(hs, W_qkv, mixed_ptr, BL, CONV_DIM, DD);
    gemm_tf32<<<dim3(VAL_DIM/128, BL/128), 256, GEMM_SMEM_BYTES>>>(hs, W_z, z_ptr, BL, VAL_DIM, DD);
    bg_kernel<<<BL, 128>>>(hs, W_b, W_a, dt_bias, A_log);
    conv_kernel<<<dim3(CONV_DIM/128, BL), 128>>>(conv_w);
    scan_kernel<<<dim3(HV, BB), 128>>>();
    gatednorm_kernel<<<dim3(HV, BL), 128>>>(norm_w);
    gemm_tf32<<<dim3(DD/128, BL/128), 256, GEMM_SMEM_BYTES>>>(gated_ptr, W_out, out, BL, DD, VAL_DIM);
}

// round 4
// speedup vs baseline: 3.0539x; 1.6364x over previous
#include <cuda_runtime.h>
#include <cuda_fp16.h>
#include <math.h>
#include <stdint.h>

#define BB 2
#define LL 2048
#define DD 2048
#define HV 32
#define HK 16
#define DK 128
#define DV 128
#define KCONV 4
#define KEY_DIM 2048
#define VAL_DIM 4096
#define CONV_DIM 8192
#define BL (BB*LL)

// fp32 intermediates
__device__ float g_mixed[(size_t)BL * CONV_DIM];
__device__ float g_conv [(size_t)BL * CONV_DIM];
__device__ float g_z    [(size_t)BL * VAL_DIM];
__device__ float g_core [(size_t)BL * VAL_DIM];
__device__ float g_gvals[(size_t)BL * HV];
__device__ float g_beta [(size_t)BL * HV];
// fp16 operands
__device__ __half g_hsh   [(size_t)BL * DD];
__device__ __half g_wqkvh [(size_t)CONV_DIM * DD];   // [N][K] transposed
__device__ __half g_wzh   [(size_t)VAL_DIM * DD];    // [N][K]
__device__ __half g_wouth [(size_t)DD * VAL_DIM];    // [N][K]
__device__ __half g_gatedh[(size_t)BL * VAL_DIM];

// ---------------------------------------------------------------------------
// fp32 -> fp16 elementwise (n % 4 == 0)
// ---------------------------------------------------------------------------
__global__ __launch_bounds__(256) void f2h_kernel(
    const float* __restrict__ src, __half* __restrict__ dst, int n4)
{
    int i = blockIdx.x * 256 + threadIdx.x;
    if (i >= n4) return;
    float4 v = ((const float4*)src)[i];
    __half2 h0 = __floats2half2_rn(v.x, v.y);
    __half2 h1 = __floats2half2_rn(v.z, v.w);
    uint2 u;
    u.x = *(uint32_t*)&h0;
    u.y = *(uint32_t*)&h1;
    ((uint2*)dst)[i] = u;
}

// ---------------------------------------------------------------------------
// fp32 [R][Nc] -> fp16 transposed [Nc][R]; R,Nc % 32 == 0
// ---------------------------------------------------------------------------
__global__ __launch_bounds__(256) void transpose_f2h(
    const float* __restrict__ src, __half* __restrict__ dst, int R, int Nc)
{
    __shared__ float tile[32][33];
    const int x  = blockIdx.x * 32 + threadIdx.x;
    const int y0 = blockIdx.y * 32 + threadIdx.y;
    #pragma unroll
    for (int j = 0; j < 4; j++)
        tile[threadIdx.y + j * 8][threadIdx.x] = src[(size_t)(y0 + j * 8) * Nc + x];
    __syncthreads();
    const int nx  = blockIdx.y * 32 + threadIdx.x;
    const int ny0 = blockIdx.x * 32 + threadIdx.y;
    #pragma unroll
    for (int j = 0; j < 4; j++)
        dst[(size_t)(ny0 + j * 8) * R + nx] =
            __float2half_rn(tile[threadIdx.x][threadIdx.y + j * 8]);
}

// ---------------------------------------------------------------------------
// fp16 tensor-core GEMM, 4-stage cp.async pipeline.
// C[M,N] = A[M,K] @ Bt[N,K]^T ; A,Bt fp16 row-major, C fp32.
// M,N % 128 == 0, K % 32 == 0. 128x128 CTA tile, BK=32/stage, m16n8k16.
// ---------------------------------------------------------------------------
#define HSTAGES 4
#define ROW_W 20                      // 32-bit words per smem row (32 halves + 8 pad)
#define HA_SZ_W (128 * ROW_W)
#define HSTAGE_W (2 * HA_SZ_W)
#define GEMM_SMEM_BYTES (HSTAGES * HSTAGE_W * 4)   // 81920

__device__ __forceinline__ void cp16(uint32_t dst, const void* src) {
    asm volatile("cp.async.cg.shared.global [%0], [%1], 16;\n" :: "r"(dst), "l"(src));
}

__global__ __launch_bounds__(256, 2) void gemm_f16(
    const __half* __restrict__ A, const __half* __restrict__ Bt,
    float* __restrict__ C, int M, int N, int K)
{
    extern __shared__ uint32_t smw[];
    uint32_t smb;
    asm("{ .reg .u64 t; cvta.to.shared.u64 t, %1; cvt.u32.u64 %0, t; }"
        : "=r"(smb) : "l"(smw));

    const int tid  = threadIdx.x;
    const int warp = tid >> 5;
    const int lane = tid & 31;
    const int g    = lane >> 2;
    const int t    = lane & 3;

    const int wm = (warp >> 2) * 64;
    const int wn = (warp & 3)  * 32;

    const int brow = blockIdx.y;
    const int bcol = blockIdx.x;

    const __half* Ab = A  + (size_t)brow * 128 * K;
    const __half* Bb = Bt + (size_t)bcol * 128 * K;

    // 512 16B-chunks per operand per stage; 256 threads -> 2 each
    const int r0 = tid >> 2;           // rows r0, r0+64
    const int cc = tid & 3;            // 16B chunk within 64B row

    float acc[4][4][4];
    #pragma unroll
    for (int mi = 0; mi < 4; mi++)
        #pragma unroll
        for (int ni = 0; ni < 4; ni++)
            #pragma unroll
            for (int r = 0; r < 4; r++) acc[mi][ni][r] = 0.f;

    const int nt = K >> 5;

    #pragma unroll
    for (int s = 0; s < HSTAGES - 1; s++) {
        const int k0 = s * 32;
        uint32_t sb = smb + (uint32_t)(s * HSTAGE_W) * 4u;
        cp16(sb + (uint32_t)(r0 * ROW_W + cc * 4) * 4u,        Ab + (size_t)r0 * K + k0 + cc * 8);
        cp16(sb + (uint32_t)((r0 + 64) * ROW_W + cc * 4) * 4u, Ab + (size_t)(r0 + 64) * K + k0 + cc * 8);
        uint32_t bbs = sb + (uint32_t)HA_SZ_W * 4u;
        cp16(bbs + (uint32_t)(r0 * ROW_W + cc * 4) * 4u,        Bb + (size_t)r0 * K + k0 + cc * 8);
        cp16(bbs + (uint32_t)((r0 + 64) * ROW_W + cc * 4) * 4u, Bb + (size_t)(r0 + 64) * K + k0 + cc * 8);
        asm volatile("cp.async.commit_group;\n");
    }

    for (int kt = 0; kt < nt; kt++) {
        asm volatile("cp.async.wait_group %0;\n" :: "n"(HSTAGES - 2));
        __syncthreads();

        const int pf = kt + HSTAGES - 1;
        if (pf < nt) {
            const int k0 = pf * 32;
            uint32_t sb = smb + (uint32_t)((pf % HSTAGES) * HSTAGE_W) * 4u;
            cp16(sb + (uint32_t)(r0 * ROW_W + cc * 4) * 4u,        Ab + (size_t)r0 * K + k0 + cc * 8);
            cp16(sb + (uint32_t)((r0 + 64) * ROW_W + cc * 4) * 4u, Ab + (size_t)(r0 + 64) * K + k0 + cc * 8);
            uint32_t bbs = sb + (uint32_t)HA_SZ_W * 4u;
            cp16(bbs + (uint32_t)(r0 * ROW_W + cc * 4) * 4u,        Bb + (size_t)r0 * K + k0 + cc * 8);
            cp16(bbs + (uint32_t)((r0 + 64) * ROW_W + cc * 4) * 4u, Bb + (size_t)(r0 + 64) * K + k0 + cc * 8);
        }
        asm volatile("cp.async.commit_group;\n");

        const uint32_t* as = smw + (size_t)(kt % HSTAGES) * HSTAGE_W;
        const uint32_t* bs = as + HA_SZ_W;

        #pragma unroll
        for (int ks = 0; ks < 2; ks++) {
            const int kw = ks * 8;
            uint32_t af[4][4], bf[4][2];
            #pragma unroll
            for (int mi = 0; mi < 4; mi++) {
                const int rb = wm + mi * 16;
                af[mi][0] = as[(rb + g    ) * ROW_W + kw + t    ];
                af[mi][1] = as[(rb + g + 8) * ROW_W + kw + t    ];
                af[mi][2] = as[(rb + g    ) * ROW_W + kw + t + 4];
                af[mi][3] = as[(rb + g + 8) * ROW_W + kw + t + 4];
            }
            #pragma unroll
            for (int ni = 0; ni < 4; ni++) {
                const int nb = wn + ni * 8;
                bf[ni][0] = bs[(nb + g) * ROW_W + kw + t    ];
                bf[ni][1] = bs[(nb + g) * ROW_W + kw + t + 4];
            }
            #pragma unroll
            for (int mi = 0; mi < 4; mi++)
                #pragma unroll
                for (int ni = 0; ni < 4; ni++) {
                    asm volatile(
                        "mma.sync.aligned.m16n8k16.row.col.f32.f16.f16.f32 "
                        "{%0,%1,%2,%3}, {%4,%5,%6,%7}, {%8,%9}, {%0,%1,%2,%3};"
                        : "+f"(acc[mi][ni][0]), "+f"(acc[mi][ni][1]),
                          "+f"(acc[mi][ni][2]), "+f"(acc[mi][ni][3])
                        : "r"(af[mi][0]), "r"(af[mi][1]), "r"(af[mi][2]), "r"(af[mi][3]),
                          "r"(bf[ni][0]), "r"(bf[ni][1]));
                }
        }
    }

    #pragma unroll
    for (int mi = 0; mi < 4; mi++) {
        #pragma unroll
        for (int ni = 0; ni < 4; ni++) {
            const size_t rr = (size_t)(brow * 128 + wm + mi * 16 + g);
            const size_t ccg = (size_t)(bcol * 128 + wn + ni * 8 + 2 * t);
            float2 v0 = make_float2(acc[mi][ni][0], acc[mi][ni][1]);
            float2 v1 = make_float2(acc[mi][ni][2], acc[mi][ni][3]);
            *(float2*)&C[rr * N + ccg]       = v0;
            *(float2*)&C[(rr + 8) * N + ccg] = v1;
        }
    }
}

// ---------------------------------------------------------------------------
// beta / g projections + activations
// ---------------------------------------------------------------------------
__global__ __launch_bounds__(128) void bg_kernel(
    const float* __restrict__ hs, const float* __restrict__ W_b,
    const float* __restrict__ W_a, const float* __restrict__ dt_bias,
    const float* __restrict__ A_log)
{
    __shared__ float row[DD];
    const int bl  = blockIdx.x;
    const int tid = threadIdx.x;

    for (int i = tid; i < DD; i += 128)
        row[i] = hs[(size_t)bl * DD + i];
    __syncthreads();

    if (tid < 64) {
        const int h = tid & 31;
        const bool isA = tid >= 32;
        const float* W = isA ? W_a : W_b;
        float acc = 0.f;
        #pragma unroll 8
        for (int i = 0; i < DD; i++)
            acc = fmaf(row[i], W[i * HV + h], acc);
        if (isA) {
            float x  = acc + dt_bias[h];
            float sp = (x > 20.f) ? x : log1pf(expf(x));
            g_gvals[(size_t)bl * HV + h] = -expf(A_log[h]) * sp;
        } else {
            g_beta[(size_t)bl * HV + h] = 1.f / (1.f + expf(-acc));
        }
    }
}

// ---------------------------------------------------------------------------
// causal depthwise conv(K=4) + SiLU + l2norm(q,k) + q*DK^-0.5
// ---------------------------------------------------------------------------
__global__ __launch_bounds__(128) void conv_kernel(const float* __restrict__ conv_w)
{
    const int grp = blockIdx.x;
    const int bl  = blockIdx.y;
    const int l   = bl & (LL - 1);
    const int tid = threadIdx.x;
    const int c   = grp * 128 + tid;

    const float w0 = conv_w[c * 4 + 0];
    const float w1 = conv_w[c * 4 + 1];
    const float w2 = conv_w[c * 4 + 2];
    const float w3 = conv_w[c * 4 + 3];

    const size_t base = (size_t)bl * CONV_DIM + c;
    float acc = g_mixed[base] * w3;
    if (l >= 1) acc = fmaf(g_mixed[base - 1 * CONV_DIM], w2, acc);
    if (l >= 2) acc = fmaf(g_mixed[base - 2 * CONV_DIM], w1, acc);
    if (l >= 3) acc = fmaf(g_mixed[base - 3 * CONV_DIM], w0, acc);

    float s = acc / (1.f + expf(-acc));

    if (grp < 32) {
        __shared__ float red[4];
        float ss = s * s;
        #pragma unroll
        for (int o = 16; o; o >>= 1)
            ss += __shfl_xor_sync(0xffffffffu, ss, o);
        if ((tid & 31) == 0) red[tid >> 5] = ss;
        __syncthreads();
        float tot = red[0] + red[1] + red[2] + red[3];
        s *= rsqrtf(tot + 1e-6f);
        if (grp < 16) s *= 0.08838834764831845f;
    }
    g_conv[base] = s;
}

// ---------------------------------------------------------------------------
// Gated delta-rule scan v2: grid (HV, BB, 2). Block handles one DV-half (64
// cols); 128 threads = 64 cols x 2-way k-split; partials combined via smem.
// ---------------------------------------------------------------------------
__global__ __launch_bounds__(128) void scan_kernel()
{
    const int h    = blockIdx.x;
    const int b    = blockIdx.y;
    const int half = blockIdx.z;
    const int tid  = threadIdx.x;
    const int col  = tid & 63;
    const int kh   = tid >> 6;       // k-half owner
    const int hk   = h >> 1;

    __shared__ float ksm[128];
    __shared__ float qsm[128];
    __shared__ float pkv[2][64];
    __shared__ float po [2][64];

    float S[64];
    #pragma unroll
    for (int i = 0; i < 64; i++) S[i] = 0.f;

    const size_t rowbase = (size_t)b * LL * CONV_DIM;
    const int qc = hk * 128 + tid;
    const int kc = KEY_DIM + hk * 128 + tid;
    const int vc = 2 * KEY_DIM + h * 128 + half * 64 + col;

    for (int t = 0; t < LL; t++) {
        const size_t off = rowbase + (size_t)t * CONV_DIM;
        ksm[tid] = g_conv[off + kc];
        qsm[tid] = g_conv[off + qc];
        const float vt = g_conv[off + vc];
        const int sidx = (b * LL + t) * HV + h;
        const float gt = g_gvals[sidx];
        const float bt = g_beta[sidx];
        __syncthreads();

        const float eg = expf(gt);
        const float* kp = ksm + kh * 64;
        const float* qp = qsm + kh * 64;

        float kv = 0.f;
        #pragma unroll
        for (int j = 0; j < 64; j++) {
            S[j] *= eg;
            kv = fmaf(kp[j], S[j], kv);
        }
        pkv[kh][col] = kv;
        __syncthreads();

        const float delta = (vt - pkv[0][col] - pkv[1][col]) * bt;

        float o = 0.f;
        #pragma unroll
        for (int j = 0; j < 64; j++) {
            S[j] = fmaf(kp[j], delta, S[j]);
            o = fmaf(qp[j], S[j], o);
        }
        po[kh][col] = o;
        __syncthreads();

        if (kh == 0)
            g_core[((size_t)(b * LL + t)) * VAL_DIM + h * 128 + half * 64 + col]
                = po[0][col] + po[1][col];
    }
}

// ---------------------------------------------------------------------------
// Gated RMSNorm -> fp16 output for final GEMM
// ---------------------------------------------------------------------------
__global__ __launch_bounds__(128) void gatednorm_kernel(const float* __restrict__ norm_w)
{
    const int h   = blockIdx.x;
    const int bl  = blockIdx.y;
    const int tid = threadIdx.x;
    const size_t idx = (size_t)bl * VAL_DIM + h * 128 + tid;

    float c  = g_core[idx];
    float zz = g_z[idx];
    float gz = zz / (1.f + expf(-zz));
    float x  = c * gz;

    __shared__ float red[4];
    float ss = x * x;
    #pragma unroll
    for (int o = 16; o; o >>= 1)
        ss += __shfl_xor_sync(0xffffffffu, ss, o);
    if ((tid & 31) == 0) red[tid >> 5] = ss;
    __syncthreads();
    float tot  = red[0] + red[1] + red[2] + red[3];
    float mean = tot * (1.f / 128.f);

    g_gatedh[idx] = __float2half_rn(x * rsqrtf(mean + 1e-6f) * norm_w[tid]);
}

// ---------------------------------------------------------------------------
extern "C" void kernel_launch(void* const* d_in, const int* in_sizes, int n_in,
                              void* d_out, int out_size)
{
    const float* hs      = (const float*)d_in[0];
    const float* W_qkv   = (const float*)d_in[1];
    const float* W_z     = (const float*)d_in[2];
    const float* W_b     = (const float*)d_in[3];
    const float* W_a     = (const float*)d_in[4];
    const float* conv_w  = (const float*)d_in[5];
    const float* dt_bias = (const float*)d_in[6];
    const float* A_log   = (const float*)d_in[7];
    const float* norm_w  = (const float*)d_in[8];
    const float* W_out   = (const float*)d_in[9];
    float* out = (float*)d_out;

    float*  mixed_ptr; cudaGetSymbolAddress((void**)&mixed_ptr, g_mixed);
    float*  z_ptr;     cudaGetSymbolAddress((void**)&z_ptr,     g_z);
    __half* hsh;       cudaGetSymbolAddress((void**)&hsh,       g_hsh);
    __half* wqkvh;     cudaGetSymbolAddress((void**)&wqkvh,     g_wqkvh);
    __half* wzh;       cudaGetSymbolAddress((void**)&wzh,       g_wzh);
    __half* wouth;     cudaGetSymbolAddress((void**)&wouth,     g_wouth);
    __half* gatedh;    cudaGetSymbolAddress((void**)&gatedh,    g_gatedh);

    cudaFuncSetAttribute(gemm_f16,
        cudaFuncAttributeMaxDynamicSharedMemorySize, GEMM_SMEM_BYTES);

    // fp16 conversions (+ weight transposes to [N][K])
    f2h_kernel<<<(BL * DD / 4 + 255) / 256, 256>>>(hs, hsh, BL * DD / 4);
    transpose_f2h<<<dim3(CONV_DIM / 32, DD / 32), dim3(32, 8)>>>(W_qkv, wqkvh, DD, CONV_DIM);
    transpose_f2h<<<dim3(VAL_DIM / 32, DD / 32), dim3(32, 8)>>>(W_z, wzh, DD, VAL_DIM);
    transpose_f2h<<<dim3(DD / 32, VAL_DIM / 32), dim3(32, 8)>>>(W_out, wouth, VAL_DIM, DD);

    gemm_f16<<<dim3(CONV_DIM/128, BL/128), 256, GEMM_SMEM_BYTES>>>(hsh, wqkvh, mixed_ptr, BL, CONV_DIM, DD);
    gemm_f16<<<dim3(VAL_DIM/128, BL/128), 256, GEMM_SMEM_BYTES>>>(hsh, wzh, z_ptr, BL, VAL_DIM, DD);
    bg_kernel<<<BL, 128>>>(hs, W_b, W_a, dt_bias, A_log);
    conv_kernel<<<dim3(CONV_DIM/128, BL), 128>>>(conv_w);
    scan_kernel<<<dim3(HV, BB, 2), 128>>>();
    gatednorm_kernel<<<dim3(HV, BL), 128>>>(norm_w);
    gemm_f16<<<dim3(DD/128, BL/128), 256, GEMM_SMEM_BYTES>>>(gatedh, wouth, out, BL, DD, VAL_DIM);
}